// round 4
// baseline (speedup 1.0000x reference)
#include <cuda_runtime.h>
#include <math.h>
#include <string.h>

#define HQ    16
#define GRP   4
#define TOPK  16
#define DQK   192
#define DV    128
#define QT    64
#define THREADS 512
#define KTP   66     // EVEN: float2 kT loads stay 8B-aligned
#define PPAD  65     // p row: 64 real q + 1 dummy col (index 64)
#define NBITS 32
#define SMSCALE 0.07216878364870322f

// smem floats:
//  qs   [65][192] = 12480  (row 64 = dummy query, zeroed)
//  kT   [192][66] = 12672  (single buffer)
//  vs   2x[64][128] = 16384
//  ps   2x[64][65]  =  8320
//  ms/ls [65] each, scl 2x[65]
//  selm[64]u, list 2x[64]i, nsel[2], jlist[33], njs, union
#define SMEM_FLOATS (12480 + 12672 + 16384 + 8320 + 65*4 + 64 + 128 + 2 + 33 + 1 + 1)
#define SMEM_BYTES  (SMEM_FLOATS * 4)

__device__ __forceinline__ void ffma2(float2& d, const float2 a, const float2 b) {
    unsigned long long ua, ub;
    memcpy(&ua, &a, 8); memcpy(&ub, &b, 8);
    unsigned long long* pd = reinterpret_cast<unsigned long long*>(&d);
    asm("fma.rn.f32x2 %0, %1, %2, %0;" : "+l"(*pd) : "l"(ua), "l"(ub));
}
__device__ __forceinline__ void fmul2(float2& d, const float2 b) {
    unsigned long long ub;
    memcpy(&ub, &b, 8);
    unsigned long long* pd = reinterpret_cast<unsigned long long*>(&d);
    asm("mul.rn.f32x2 %0, %0, %1;" : "+l"(*pd) : "l"(ub));
}
__device__ __forceinline__ void cp_async4(float* smem, const float* g) {
    unsigned s = (unsigned)__cvta_generic_to_shared(smem);
    asm volatile("cp.async.ca.shared.global [%0], [%1], 4;" :: "r"(s), "l"(g) : "memory");
}
__device__ __forceinline__ void cp_async16(float* smem, const float* g) {
    unsigned s = (unsigned)__cvta_generic_to_shared(smem);
    asm volatile("cp.async.cg.shared.global [%0], [%1], 16;" :: "r"(s), "l"(g) : "memory");
}
__device__ __forceinline__ void cp_commit() {
    asm volatile("cp.async.commit_group;" ::: "memory");
}
__device__ __forceinline__ void cp_wait0() {
    asm volatile("cp.async.wait_group 0;" ::: "memory");
}

__global__ __launch_bounds__(THREADS, 1)
void selattn_kernel(const float* __restrict__ q, const float* __restrict__ k,
                    const float* __restrict__ v, const int* __restrict__ sidx,
                    const int* __restrict__ slp, float* __restrict__ out) {
    extern __shared__ float sh[];
    float* qs  = sh;                         // [65][192]
    float* kT  = qs + 65 * DQK;              // [192][66]
    float* vsb[2]; vsb[0] = kT + DQK * KTP; vsb[1] = vsb[0] + 64 * DV;
    float* psb[2]; psb[0] = vsb[1] + 64 * DV; psb[1] = psb[0] + 64 * PPAD;
    float* ms  = psb[1] + 64 * PPAD;         // [65]
    float* ls  = ms + 65;                    // [65]
    float* sclb[2]; sclb[0] = ls + 65; sclb[1] = sclb[0] + 65;
    unsigned* selm = (unsigned*)(sclb[1] + 65);  // [64]
    int* listb[2]; listb[0] = (int*)(selm + 64); listb[1] = listb[0] + 64;
    int* nselb  = listb[1] + 64;             // [2]
    int* jlist  = nselb + 2;                 // [33]
    int* njsp   = jlist + 33;
    unsigned* unionp = (unsigned*)(njsp + 1);

    const int S    = slp ? slp[0] : 2048;
    const int qt   = blockIdx.x;
    const int h    = blockIdx.y;
    const int g    = h >> 2;
    const int t0   = qt * QT;
    const int seq0 = (t0 / S) * S;
    const int tid  = threadIdx.x;
    const int lane = tid & 31;
    const int w    = tid >> 5;

    // ---- prologue: Q tile, selection masks, union, active-block list ----
    for (int f = tid; f < QT * (DQK / 4); f += THREADS) {
        int qi = f / (DQK / 4), dq = f % (DQK / 4);
        ((float4*)qs)[qi * (DQK / 4) + dq] =
            ((const float4*)(q + (size_t)(t0 + qi) * HQ * DQK + (size_t)h * DQK))[dq];
    }
    if (tid < DQK) qs[QT * DQK + tid] = 0.0f;   // dummy query row
    if (tid < QT)  selm[tid] = 0u;
    if (tid < 65) { ms[tid] = -1e30f; ls[tid] = 0.0f; }
    __syncthreads();

    for (int f = tid; f < QT * TOPK; f += THREADS) {
        int qi = f >> 4, kk = f & 15;
        int b = sidx[(size_t)(t0 + qi) * (GRP * TOPK) + g * TOPK + kk] & 31;
        atomicOr(&selm[qi], 1u << b);
    }
    __syncthreads();
    if (tid < QT) {
        int tq = (t0 + tid) - seq0;
        int bt = tq >> 6;
        unsigned causal = (bt >= 31) ? 0xffffffffu : ((1u << (bt + 1)) - 1u);
        selm[tid] &= causal;
    }
    __syncthreads();
    if (tid < 32) {
        unsigned u = selm[tid] | selm[tid + 32];
        #pragma unroll
        for (int o = 16; o; o >>= 1) u |= __shfl_xor_sync(0xffffffffu, u, o);
        if (tid == 0) *unionp = u;
    }
    __syncthreads();
    if (tid == 0) {
        unsigned u = *unionp;
        int n = 0;
        for (int j = 0; j < NBITS; j++)
            if ((u >> j) & 1u) jlist[n++] = j;
        *njsp = n;
    }
    __syncthreads();
    const int njs = *njsp;

    // ---- fill(jn, bn): cp.async K-transpose + V, zero ps, reset scl, compact ----
    auto do_fill = [&](int jn, int bn) {
        const float* kblk = k + ((size_t)(seq0 + jn * 64) * HQ + h) * DQK;
        for (int f = tid; f < 64 * DQK; f += THREADS) {
            int s = f / DQK, d = f - s * DQK;
            cp_async4(kT + d * KTP + s, kblk + (size_t)s * HQ * DQK + d);
        }
        const float* vblk = v + ((size_t)(seq0 + jn * 64) * HQ + h) * DV;
        float* vd = vsb[bn];
        for (int f = tid; f < 64 * (DV / 4); f += THREADS) {
            int s = f >> 5, c = f & 31;
            cp_async16(vd + s * DV + c * 4, vblk + (size_t)s * HQ * DV + c * 4);
        }
        cp_commit();
        float2* pz = (float2*)psb[bn];
        for (int f = tid; f < (64 * PPAD) / 2; f += THREADS)
            pz[f] = make_float2(0.f, 0.f);
        if (tid < 65) sclb[bn][tid] = 1.0f;
        if (w == 0) {
            int* lb = listb[bn];
            lb[lane] = 64; lb[lane + 32] = 64;
            __syncwarp();
            bool a0 = (selm[lane]      >> jn) & 1u;
            bool a1 = (selm[lane + 32] >> jn) & 1u;
            unsigned b0 = __ballot_sync(0xffffffffu, a0);
            unsigned b1 = __ballot_sync(0xffffffffu, a1);
            unsigned lt = (1u << lane) - 1u;
            if (a0) lb[__popc(b0 & lt)] = lane;
            if (a1) lb[__popc(b0) + __popc(b1 & lt)] = lane + 32;
            if (lane == 0) nselb[bn] = __popc(b0) + __popc(b1);
        }
    };

    if (njs > 0) do_fill(jlist[0], 0);
    cp_wait0();
    __syncthreads();

    // ---- PV static ownership: warp = 16q x 32d, lane = 1q x 16d ----
    const int pvq = (w & 3) * 16 + (lane & 15);
    const int pvd = (w >> 2) * 32 + (lane >> 4) * 16;
    float2 acc[8];
    #pragma unroll
    for (int i = 0; i < 8; i++) acc[i] = make_float2(0.0f, 0.0f);

    for (int ii = 0; ii < njs; ii++) {
        const int b = ii & 1;
        const int j = jlist[ii];
        float* ps  = psb[b];
        float* scl = sclb[b];

        // ---- score phase: c=4 queries per warp ----
        const int nsel = nselb[b];
        const int nw = (nsel + 3) >> 2;
        if (w < nw) {
            int qi[4]; const float* qp[4];
            #pragma unroll
            for (int u = 0; u < 4; u++) {
                qi[u] = listb[b][w * 4 + u];
                qp[u] = qs + qi[u] * DQK;
            }
            float s0[4] = {0.f, 0.f, 0.f, 0.f};
            float s1[4] = {0.f, 0.f, 0.f, 0.f};
            const float* kr = kT + 2 * lane;
            #pragma unroll 2
            for (int d = 0; d < DQK; d += 4) {
                const float2 k0 = *(const float2*)(kr + (d + 0) * KTP);
                const float2 k1 = *(const float2*)(kr + (d + 1) * KTP);
                const float2 k2 = *(const float2*)(kr + (d + 2) * KTP);
                const float2 k3 = *(const float2*)(kr + (d + 3) * KTP);
                #pragma unroll
                for (int u = 0; u < 4; u++) {
                    const float4 f = *(const float4*)(qp[u] + d);
                    s0[u] += f.x * k0.x; s1[u] += f.x * k0.y;
                    s0[u] += f.y * k1.x; s1[u] += f.y * k1.y;
                    s0[u] += f.z * k2.x; s1[u] += f.z * k2.y;
                    s0[u] += f.w * k3.x; s1[u] += f.w * k3.y;
                }
            }
            const int sg = j * 64 + 2 * lane;
            #pragma unroll
            for (int u = 0; u < 4; u++) {
                const int tq = t0 + qi[u] - seq0;
                float a0 = (sg     <= tq) ? s0[u] * SMSCALE : -1e30f;
                float a1 = (sg + 1 <= tq) ? s1[u] * SMSCALE : -1e30f;
                float mx = fmaxf(a0, a1);
                #pragma unroll
                for (int o = 16; o; o >>= 1)
                    mx = fmaxf(mx, __shfl_xor_sync(0xffffffffu, mx, o));
                const float mo = ms[qi[u]];
                const float mn = fmaxf(mo, mx);
                const float p0 = __expf(a0 - mn), p1 = __expf(a1 - mn);
                float r = p0 + p1;
                #pragma unroll
                for (int o = 16; o; o >>= 1)
                    r += __shfl_xor_sync(0xffffffffu, r, o);
                ps[(2 * lane)     * PPAD + qi[u]] = p0;
                ps[(2 * lane + 1) * PPAD + qi[u]] = p1;
                if (lane == 0) {
                    float sc = __expf(mo - mn);
                    scl[qi[u]] = sc;
                    ls[qi[u]] = ls[qi[u]] * sc + r;
                    ms[qi[u]] = mn;
                }
            }
        }
        __syncthreads();

        // ---- fill(j+1) overlapped with PV(j) ----
        if (ii + 1 < njs) do_fill(jlist[ii + 1], b ^ 1);

        {
            const float sc = scl[pvq];
            const float2 scp = make_float2(sc, sc);
            #pragma unroll
            for (int i = 0; i < 8; i++) fmul2(acc[i], scp);
            const float* vbase = vsb[b] + pvd;
            #pragma unroll 4
            for (int s = 0; s < 64; s++) {
                const float p = ps[s * PPAD + pvq];
                const float2 pp = make_float2(p, p);
                const float4* vp = (const float4*)(vbase + s * DV);
                const float4 a0 = vp[0], a1 = vp[1], a2 = vp[2], a3 = vp[3];
                ffma2(acc[0], make_float2(a0.x, a0.y), pp);
                ffma2(acc[1], make_float2(a0.z, a0.w), pp);
                ffma2(acc[2], make_float2(a1.x, a1.y), pp);
                ffma2(acc[3], make_float2(a1.z, a1.w), pp);
                ffma2(acc[4], make_float2(a2.x, a2.y), pp);
                ffma2(acc[5], make_float2(a2.z, a2.w), pp);
                ffma2(acc[6], make_float2(a3.x, a3.y), pp);
                ffma2(acc[7], make_float2(a3.z, a3.w), pp);
            }
        }
        cp_wait0();
        __syncthreads();
    }

    // ---- finalize ----
    const float invl = 1.0f / ls[pvq];
    float* op = out + (size_t)(t0 + pvq) * (HQ * DV) + (size_t)h * DV + pvd;
    float4 o0, o1, o2, o3;
    o0.x = acc[0].x * invl; o0.y = acc[0].y * invl; o0.z = acc[1].x * invl; o0.w = acc[1].y * invl;
    o1.x = acc[2].x * invl; o1.y = acc[2].y * invl; o1.z = acc[3].x * invl; o1.w = acc[3].y * invl;
    o2.x = acc[4].x * invl; o2.y = acc[4].y * invl; o2.z = acc[5].x * invl; o2.w = acc[5].y * invl;
    o3.x = acc[6].x * invl; o3.y = acc[6].y * invl; o3.z = acc[7].x * invl; o3.w = acc[7].y * invl;
    *(float4*)(op)      = o0;
    *(float4*)(op + 4)  = o1;
    *(float4*)(op + 8)  = o2;
    *(float4*)(op + 12) = o3;
}

extern "C" void kernel_launch(void* const* d_in, const int* in_sizes, int n_in,
                              void* d_out, int out_size) {
    const float* q   = (const float*)d_in[0];
    const float* k   = (const float*)d_in[1];
    const float* v   = (const float*)d_in[2];
    const int*   idx = (const int*)d_in[3];
    const int*   slp = (n_in >= 6) ? (const int*)d_in[5] : nullptr;
    float* out = (float*)d_out;

    const int T = in_sizes[0] / (HQ * DQK);

    static bool attr_set = false;
    if (!attr_set) {
        cudaFuncSetAttribute(selattn_kernel,
                             cudaFuncAttributeMaxDynamicSharedMemorySize, SMEM_BYTES);
        attr_set = true;
    }

    dim3 grid(T / QT, HQ);
    selattn_kernel<<<grid, THREADS, SMEM_BYTES>>>(q, k, v, idx, slp, out);
}